// round 3
// baseline (speedup 1.0000x reference)
#include <cuda_runtime.h>
#include <cuda_bf16.h>
#include <math.h>
#include <stdint.h>

#define B 2
#define P 512
#define C 21
#define REG 5
#define DET 100
#define NGRP (B*(C-1))          // 40
#define NPROP (B*P)             // 1024
#define SCORE_THRESH 0.05f
#define NMS_THR 0.5f
#define BBOX_CLIP 4.135166556742356f   // log(1000/16)
#define DEG2RAD 0.017453292519943295f
#define RAD2DEG 57.29577951308232f
#define IMW_M1 1023.0f
#define IMH_M1 799.0f
#define QCAP 131072
#define SQ_CAP 8192
#define FULLM 0xffffffffu

// ---------------- device scratch ----------------
__device__ float g_scores[NPROP * C];            // softmax scores
__device__ float g_props[NPROP * C * 5];         // decoded rotated boxes
__device__ float g_bb[NPROP * C * 4];            // clipped axis-aligned boxes
__device__ float g_pr_s[NGRP * P * 5];           // sorted proposals
__device__ float g_bx_s[NGRP * P * 4];           // sorted aabb boxes
__device__ float g_msk[B * (C-1) * P];           // post-NMS masked scores
__device__ int   g_queue[NGRP * QCAP];           // pair-queue overflow

// ---------------- kernel 1: softmax + decode + bb ----------------
__global__ void k1_decode(const float* __restrict__ logits,
                          const float* __restrict__ regr,
                          const float* __restrict__ rrects)
{
    int n = blockIdx.x * blockDim.y + threadIdx.y;   // proposal row
    int t = threadIdx.x;                             // 0..31 (one warp per row)

    float x = (t < C) ? logits[n * C + t] : -INFINITY;
    float m = x;
    #pragma unroll
    for (int o = 16; o; o >>= 1) m = fmaxf(m, __shfl_xor_sync(FULLM, m, o));
    float e = (t < C) ? expf(x - m) : 0.0f;
    float ssum = e;
    #pragma unroll
    for (int o = 16; o; o >>= 1) ssum += __shfl_xor_sync(FULLM, ssum, o);
    float score = e / ssum;
    if (t < C) g_scores[n * C + t] = score;

    float axc = rrects[n*5+0], ayc = rrects[n*5+1];
    float aw  = rrects[n*5+2], ah  = rrects[n*5+3];
    float aa  = rrects[n*5+4];

    if (t < C) {
        const float* d = &regr[n * C * REG + t * REG];
        float dx = d[0] / 10.0f;
        float dy = d[1] / 10.0f;
        float dw = fminf(d[2] / 5.0f, BBOX_CLIP);
        float dh = fminf(d[3] / 5.0f, BBOX_CLIP);
        float da = d[4] / 3.0f;

        float px = dx * aw + axc;
        float py = dy * ah + ayc;
        float pw = expf(dw) * aw;
        float ph = expf(dh) * ah;
        float pa = da * RAD2DEG + aa;

        float* pp = &g_props[(n * C + t) * 5];
        pp[0]=px; pp[1]=py; pp[2]=pw; pp[3]=ph; pp[4]=pa;

        float th = pa * DEG2RAD;
        float cth = cosf(th), sth = sinf(th);
        float hx = pw * 0.5f, hy = ph * 0.5f;
        float ox[4] = {-hx, hx, hx, -hx};
        float oy[4] = {-hy, -hy, hy, hy};
        float mnx =  1e30f, mny =  1e30f, mxx = -1e30f, mxy = -1e30f;
        #pragma unroll
        for (int i = 0; i < 4; i++) {
            float cx = px + cth*ox[i] - sth*oy[i];
            float cy = py + sth*ox[i] + cth*oy[i];
            mnx = fminf(mnx, cx); mxx = fmaxf(mxx, cx);
            mny = fminf(mny, cy); mxy = fmaxf(mxy, cy);
        }
        float* bb = &g_bb[(n * C + t) * 4];
        bb[0] = fminf(fmaxf(mnx, 0.0f), IMW_M1);
        bb[1] = fminf(fmaxf(mny, 0.0f), IMH_M1);
        bb[2] = fminf(fmaxf(mxx, 0.0f), IMW_M1);
        bb[3] = fminf(fmaxf(mxy, 0.0f), IMH_M1);
    }
}

// ---------------- bitonic helpers (desc by value, asc by index) -------------
__device__ __forceinline__ void cmp_shfl(float& v, int& i, int tid, int j, bool dir)
{
    float ov = __shfl_xor_sync(FULLM, v, j);
    int   oi = __shfl_xor_sync(FULLM, i, j);
    bool lower = ((tid & j) == 0);
    bool before = (v > ov) || (v == ov && i < oi);
    bool lower_before = lower ? before : !before;
    if (lower_before != dir) { v = ov; i = oi; }
}

// ---------------- exact quad-quad intersection area (matches reference) -----
__device__ float inter_area(const float* __restrict__ p1x, const float* __restrict__ p1y,
                            const float* __restrict__ p2x, const float* __restrict__ p2y)
{
    float px[8], py[8];
    #pragma unroll
    for (int i = 0; i < 4; i++) { px[i] = p1x[i]; py[i] = p1y[i]; }
    int n = 4;

    for (int k = 0; k < 4; k++) {
        float ax = p2x[k], ay = p2y[k];
        int k1 = (k + 1) & 3;
        float dx = p2x[k1] - ax, dy = p2y[k1] - ay;
        float qx[8], qy[8];
        int m = 0;
        for (int i = 0; i < n; i++) {
            float sx = px[i], sy = py[i];
            int ei = (i + 1 == n) ? 0 : (i + 1);
            float ex = px[ei], ey = py[ei];
            float cs = dx * (sy - ay) - dy * (sx - ax);
            float ce = dx * (ey - ay) - dy * (ex - ax);
            float denom = cs - ce;
            float t = cs / ((fabsf(denom) > 1e-12f) ? denom : 1e-12f);
            float ipx = sx + t * (ex - sx);
            float ipy = sy + t * (ey - sy);
            bool s_in = (cs >= 0.0f), e_in = (ce >= 0.0f);
            if (s_in != e_in) { int mm = m < 7 ? m : 7; qx[mm] = ipx; qy[mm] = ipy; m++; }
            if (e_in)         { int mm = m < 7 ? m : 7; qx[mm] = ex;  qy[mm] = ey;  m++; }
        }
        if (m > 8) m = 8;
        n = m;
        for (int i = 0; i < n; i++) { px[i] = qx[i]; py[i] = qy[i]; }
    }
    if (n < 3) return 0.0f;
    float acc = 0.0f;
    for (int i = 0; i < n; i++) {
        int k2 = (i + 1 == n) ? 0 : (i + 1);
        acc += px[i] * py[k2] - px[k2] * py[i];
    }
    return 0.5f * fabsf(acc);
}

// ---------------- kernel 2+3: per-group sort + rotated NMS ------------------
__global__ void k23_sortnms()
{
    int g = blockIdx.x;                 // 0..39
    int b = g / (C-1);
    int cls = g % (C-1) + 1;
    int tid = threadIdx.x;              // 0..511

    extern __shared__ float sm[];
    float* sv    = sm;                       // 512
    int*   si    = (int*)(sv + P);           // 512
    float* ptsx  = (float*)(si + P);         // 512*4
    float* ptsy  = ptsx + P * 4;             // 512*4
    float* bminx = ptsy + P * 4;             // 512
    float* bminy = bminx + P;
    float* bmaxx = bminy + P;
    float* bmaxy = bmaxx + P;
    float* areaS = bmaxy + P;
    unsigned* sup = (unsigned*)(areaS + P);  // 512*16
    int* squeue = (int*)(sup + P * 16);      // SQ_CAP
    __shared__ int qcnt;
    __shared__ unsigned keepM[16];
    __shared__ int Vsh;

    // ---- load + mask score ----
    float s = g_scores[(b * P + tid) * C + cls];
    float v = (s > SCORE_THRESH) ? s : -1.0f;
    int idx = tid;

    // ---- bitonic sort 512 (registers + shfl; smem only for j>=32) ----
    #pragma unroll
    for (int k = 2; k <= 32; k <<= 1) {
        bool dir = ((tid & k) == 0);
        #pragma unroll
        for (int j = k >> 1; j >= 1; j >>= 1) cmp_shfl(v, idx, tid, j, dir);
    }
    #pragma unroll
    for (int k = 64; k <= 512; k <<= 1) {
        bool dir = ((tid & k) == 0);
        #pragma unroll
        for (int j = k >> 1; j >= 32; j >>= 1) {
            sv[tid] = v; si[tid] = idx;
            __syncthreads();
            int p2 = tid ^ j;
            float ov = sv[p2]; int oi = si[p2];
            bool lower = ((tid & j) == 0);
            bool before = (v > ov) || (v == ov && idx < oi);
            bool lower_before = lower ? before : !before;
            if (lower_before != dir) { v = ov; idx = oi; }
            __syncthreads();
        }
        #pragma unroll
        for (int j = 16; j >= 1; j >>= 1) cmp_shfl(v, idx, tid, j, dir);
    }
    // thread tid now holds rank-tid element (v = masked score, idx = orig proposal)

    // ---- gather decoded box + aabb, write for output kernel ----
    int src = (b * P + idx) * C + cls;
    float pp[5];
    #pragma unroll
    for (int k = 0; k < 5; k++) { pp[k] = g_props[src * 5 + k]; g_pr_s[(g * P + tid) * 5 + k] = pp[k]; }
    #pragma unroll
    for (int k = 0; k < 4; k++) g_bx_s[(g * P + tid) * 4 + k] = g_bb[src * 4 + k];

    // ---- corner points + aabb + area into smem ----
    float th = pp[4] * DEG2RAD;
    float cth = cosf(th), sth = sinf(th);
    float hx = pp[2] * 0.5f, hy = pp[3] * 0.5f;
    float oxs[4] = {-hx, hx, hx, -hx};
    float oys[4] = {-hy, -hy, hy, hy};
    float mnx = 1e30f, mny = 1e30f, mxx = -1e30f, mxy = -1e30f;
    #pragma unroll
    for (int i = 0; i < 4; i++) {
        float cx = pp[0] + cth * oxs[i] - sth * oys[i];
        float cy = pp[1] + sth * oxs[i] + cth * oys[i];
        ptsx[tid * 4 + i] = cx;
        ptsy[tid * 4 + i] = cy;
        mnx = fminf(mnx, cx); mxx = fmaxf(mxx, cx);
        mny = fminf(mny, cy); mxy = fmaxf(mxy, cy);
    }
    bminx[tid] = mnx; bmaxx[tid] = mxx;
    bminy[tid] = mny; bmaxy[tid] = mxy;
    areaS[tid] = pp[2] * pp[3];
    #pragma unroll
    for (int k = 0; k < 16; k++) sup[tid * 16 + k] = 0u;

    bool valid = v > SCORE_THRESH;
    int V = __syncthreads_count(valid);   // valid entries form a sorted prefix
    if (tid == 0) { qcnt = 0; Vsh = V; }
    __syncthreads();

    // ---- phase 1: AABB precheck -> pair queue (ballot-aggregated push) ----
    int lane = tid & 31;
    long long M = (long long)V * (V - 1) / 2;
    for (long long base = 0; base < M; base += blockDim.x) {
        long long t = base + tid;
        bool ov = false; int pi = 0, pj = 0;
        if (t < M) {
            int i = (int)((sqrtf(8.0f * (float)t + 1.0f) + 1.0f) * 0.5f);
            while ((long long)i * (i - 1) / 2 > t) i--;
            while ((long long)(i + 1) * i / 2 <= t) i++;
            int j = (int)(t - (long long)i * (i - 1) / 2);
            ov = !(bmaxx[i] < bminx[j] || bmaxx[j] < bminx[i] ||
                   bmaxy[i] < bminy[j] || bmaxy[j] < bminy[i]);
            pi = i; pj = j;
        }
        unsigned mb = __ballot_sync(FULLM, ov);
        if (mb) {
            int ldr = __ffs(mb) - 1;
            int basep = 0;
            if (lane == ldr) basep = atomicAdd(&qcnt, __popc(mb));
            basep = __shfl_sync(FULLM, basep, ldr);
            if (ov) {
                int pos = basep + __popc(mb & ((1u << lane) - 1u));
                int enc = (pi << 16) | pj;
                if (pos < SQ_CAP) squeue[pos] = enc;
                else g_queue[g * QCAP + (pos - SQ_CAP)] = enc;
            }
        }
    }
    __syncthreads();

    // ---- phase 2: dense exact IoU over surviving pairs ----
    int nq = qcnt;
    for (int q = tid; q < nq; q += blockDim.x) {
        int ij = (q < SQ_CAP) ? squeue[q] : g_queue[g * QCAP + (q - SQ_CAP)];
        int i = ij >> 16, j = ij & 0xffff;
        float inter = inter_area(&ptsx[i * 4], &ptsy[i * 4], &ptsx[j * 4], &ptsy[j * 4]);
        float iou = inter / (areaS[i] + areaS[j] - inter + 1e-8f);
        if (iou > NMS_THR) atomicOr(&sup[i * 16 + (j >> 5)], 1u << (j & 31));
    }
    __syncthreads();

    // ---- phase 3: greedy scan (warp 0, prefetched) ----
    if (tid < 32) {
        unsigned kw = 0;
        int VV = Vsh;
        unsigned srow = (tid < 16 && VV > 0) ? sup[tid] : 0u;
        for (int i = 0; i < VV; i++) {
            unsigned nrow = (tid < 16 && (i + 1) < VV) ? sup[(i + 1) * 16 + tid] : 0u;
            bool any = __any_sync(FULLM, (kw & srow) != 0u);
            if (!any && tid == (i >> 5)) kw |= 1u << (i & 31);
            srow = nrow;
        }
        if (tid < 16) keepM[tid] = kw;
    }
    __syncthreads();

    bool kept = (tid < Vsh) && ((keepM[tid >> 5] >> (tid & 31)) & 1u);
    g_msk[g * P + tid] = kept ? v : -1.0f;
}

// ---------------- kernel 4: radix-threshold top-100 + output ----------------
#define K4_THREADS 1024
#define K4_PER (((C-1)*P) / K4_THREADS)   // 10 (exact)
#define CANDCAP 256

__global__ void k4_topk(float* __restrict__ out)
{
    int b = blockIdx.x;
    int tid = threadIdx.x;
    const int TOT = (C - 1) * P;   // 10240
    int lane = tid & 31;
    int wid = tid >> 5;

    float v[K4_PER];
    unsigned key[K4_PER];
    #pragma unroll
    for (int i = 0; i < K4_PER; i++) {
        float x = g_msk[b * TOT + tid + i * K4_THREADS];
        v[i] = x;
        unsigned bb = __float_as_uint(x);
        key[i] = bb ^ ((bb & 0x80000000u) ? 0xFFFFFFFFu : 0x80000000u);
    }

    __shared__ int partial[2][32];
    __shared__ int ncand;
    __shared__ float cv[CANDCAP];
    __shared__ int   ci[CANDCAP];

    if (tid == 0) ncand = 0;

    // binary search: largest threshold with count(key >= thr) >= DET
    unsigned cur = 0u;
    #pragma unroll
    for (int bit = 31; bit >= 0; bit--) {
        unsigned trial = cur | (1u << bit);
        int c = 0;
        #pragma unroll
        for (int i = 0; i < K4_PER; i++) c += (key[i] >= trial);
        #pragma unroll
        for (int o = 16; o; o >>= 1) c += __shfl_xor_sync(FULLM, c, o);
        if (lane == 0) partial[bit & 1][wid] = c;
        __syncthreads();
        int t = partial[bit & 1][lane];
        #pragma unroll
        for (int o = 16; o; o >>= 1) t += __shfl_xor_sync(FULLM, t, o);
        if (t >= DET) cur = trial;
    }
    unsigned kthr = cur;

    // collect candidates (ballot-aggregated): key >= kthr AND positive value
    __syncthreads();
    #pragma unroll
    for (int i = 0; i < K4_PER; i++) {
        bool cand = (key[i] >= kthr) && (v[i] > 0.0f);
        unsigned mb = __ballot_sync(FULLM, cand);
        if (mb) {
            int ldr = __ffs(mb) - 1;
            int basep = 0;
            if (lane == ldr) basep = atomicAdd(&ncand, __popc(mb));
            basep = __shfl_sync(FULLM, basep, ldr);
            if (cand) {
                int pos = basep + __popc(mb & ((1u << lane) - 1u));
                if (pos < CANDCAP) { cv[pos] = v[i]; ci[pos] = tid + i * K4_THREADS; }
            }
        }
    }
    __syncthreads();
    int nc = min(ncand, CANDCAP);

    // bitonic sort CANDCAP=256 candidates (regs + shfl; smem for j>=32)
    float mv = -1e30f; int mi = 0x7fffffff;
    if (tid < CANDCAP && tid < nc) { mv = cv[tid]; mi = ci[tid]; }
    __syncthreads();

    if (tid < CANDCAP) {
        #pragma unroll
        for (int k = 2; k <= 32; k <<= 1) {
            bool dir = ((tid & k) == 0);
            #pragma unroll
            for (int j = k >> 1; j >= 1; j >>= 1) cmp_shfl(mv, mi, tid, j, dir);
        }
    }
    #pragma unroll
    for (int k = 64; k <= CANDCAP; k <<= 1) {
        bool dir = ((tid & k) == 0);
        #pragma unroll
        for (int j = k >> 1; j >= 32; j >>= 1) {
            if (tid < CANDCAP) { cv[tid] = mv; ci[tid] = mi; }
            __syncthreads();
            if (tid < CANDCAP) {
                int p2 = tid ^ j;
                float ov = cv[p2]; int oi = ci[p2];
                bool lower = ((tid & j) == 0);
                bool before = (mv > ov) || (mv == ov && mi < oi);
                bool lower_before = lower ? before : !before;
                if (lower_before != dir) { mv = ov; mi = oi; }
            }
            __syncthreads();
        }
        if (tid < CANDCAP) {
            #pragma unroll
            for (int j = 16; j >= 1; j >>= 1) cmp_shfl(mv, mi, tid, j, dir);
        }
    }

    // output layout (float32): bb [B,DET,4] | rr [B,DET,5] | sc [B,DET] | lab [B,DET]
    if (tid < DET) {
        float val = mv;
        int fi = (mi == 0x7fffffff) ? 0 : mi;
        bool ok = val > 0.0f;
        int cls = fi / P + 1;
        int gi = b * TOT + fi;
        int o = b * DET + tid;
        #pragma unroll
        for (int jj = 0; jj < 4; jj++)
            out[o * 4 + jj] = ok ? g_bx_s[gi * 4 + jj] : 0.0f;
        #pragma unroll
        for (int jj = 0; jj < 5; jj++)
            out[B * DET * 4 + o * 5 + jj] = ok ? g_pr_s[gi * 5 + jj] : 0.0f;
        out[B * DET * 9 + o] = ok ? val : 0.0f;
        out[B * DET * 10 + o] = ok ? (float)cls : 0.0f;
    }
}

// ---------------- launch ----------------
extern "C" void kernel_launch(void* const* d_in, const int* in_sizes, int n_in,
                              void* d_out, int out_size)
{
    const float* logits = (const float*)d_in[0];
    const float* regr   = (const float*)d_in[1];
    const float* rrects = (const float*)d_in[2];
    float* out = (float*)d_out;

    const int SMEM23 = (P + P*4*2 + P*5) * (int)sizeof(float) + P * (int)sizeof(int)
                     + P*16*(int)sizeof(unsigned) + SQ_CAP*(int)sizeof(int);
    cudaFuncSetAttribute(k23_sortnms, cudaFuncAttributeMaxDynamicSharedMemorySize, SMEM23);

    k1_decode<<<NPROP/8, dim3(32,8)>>>(logits, regr, rrects);
    k23_sortnms<<<NGRP, P, SMEM23>>>();
    k4_topk<<<B, K4_THREADS>>>(out);
}

// round 5
// speedup vs baseline: 1.6347x; 1.6347x over previous
#include <cuda_runtime.h>
#include <cuda_bf16.h>
#include <math.h>
#include <stdint.h>

#define B 2
#define P 512
#define C 21
#define REG 5
#define DET 100
#define NGRP (B*(C-1))          // 40
#define NPROP (B*P)             // 1024
#define SCORE_THRESH 0.05f
#define NMS_THR 0.5f
#define BBOX_CLIP 4.135166556742356f   // log(1000/16)
#define DEG2RAD 0.017453292519943295f
#define RAD2DEG 57.29577951308232f
#define IMW_M1 1023.0f
#define IMH_M1 799.0f
#define QCAP 131072
#define SQ_CAP 4096
#define FULLM 0xffffffffu

// ---------------- device scratch ----------------
__device__ float g_pr_s[NGRP * P * 5];           // sorted proposals
__device__ float g_bx_s[NGRP * P * 4];           // sorted aabb boxes (clipped)
__device__ float g_msk[B * (C-1) * P];           // post-NMS masked scores
__device__ int   g_queue[NGRP * QCAP];           // pair-queue overflow

// ---------------- bitonic helpers (desc by value, asc by index) -------------
__device__ __forceinline__ void cmp_shfl(float& v, int& i, int tid, int j, bool dir)
{
    float ov = __shfl_xor_sync(FULLM, v, j);
    int   oi = __shfl_xor_sync(FULLM, i, j);
    bool lower = ((tid & j) == 0);
    bool before = (v > ov) || (v == ov && i < oi);
    bool lower_before = lower ? before : !before;
    if (lower_before != dir) { v = ov; i = oi; }
}

// ---------------- exact quad-quad intersection area (matches reference) -----
__device__ float inter_area(const float* __restrict__ p1x, const float* __restrict__ p1y,
                            const float* __restrict__ p2x, const float* __restrict__ p2y)
{
    float px[8], py[8];
    #pragma unroll
    for (int i = 0; i < 4; i++) { px[i] = p1x[i]; py[i] = p1y[i]; }
    int n = 4;

    for (int k = 0; k < 4; k++) {
        float ax = p2x[k], ay = p2y[k];
        int k1 = (k + 1) & 3;
        float dx = p2x[k1] - ax, dy = p2y[k1] - ay;
        float qx[8], qy[8];
        int m = 0;
        for (int i = 0; i < n; i++) {
            float sx = px[i], sy = py[i];
            int ei = (i + 1 == n) ? 0 : (i + 1);
            float ex = px[ei], ey = py[ei];
            float cs = dx * (sy - ay) - dy * (sx - ax);
            float ce = dx * (ey - ay) - dy * (ex - ax);
            float denom = cs - ce;
            float t = cs / ((fabsf(denom) > 1e-12f) ? denom : 1e-12f);
            float ipx = sx + t * (ex - sx);
            float ipy = sy + t * (ey - sy);
            bool s_in = (cs >= 0.0f), e_in = (ce >= 0.0f);
            if (s_in != e_in) { int mm = m < 7 ? m : 7; qx[mm] = ipx; qy[mm] = ipy; m++; }
            if (e_in)         { int mm = m < 7 ? m : 7; qx[mm] = ex;  qy[mm] = ey;  m++; }
        }
        if (m > 8) m = 8;
        n = m;
        for (int i = 0; i < n; i++) { px[i] = qx[i]; py[i] = qy[i]; }
    }
    if (n < 3) return 0.0f;
    float acc = 0.0f;
    for (int i = 0; i < n; i++) {
        int k2 = (i + 1 == n) ? 0 : (i + 1);
        acc += px[i] * py[k2] - px[k2] * py[i];
    }
    return 0.5f * fabsf(acc);
}

// ---------------- kernel 1+2+3: decode + sort + rotated NMS per group -------
__global__ void k123_sortnms(const float* __restrict__ logits,
                             const float* __restrict__ regr,
                             const float* __restrict__ rrects)
{
    int g = blockIdx.x;                 // 0..39
    int b = g / (C-1);
    int cls = g % (C-1) + 1;
    int tid = threadIdx.x;              // 0..511

    extern __shared__ float sm[];
    float* sv     = sm;                        // 512
    int*   si     = (int*)(sv + P);            // 512
    float* boxbuf = (float*)(si + P);          // 5*512 (SoA: [k][row])
    float* ptsx   = boxbuf + 5 * P;            // 512*4
    float* ptsy   = ptsx + P * 4;              // 512*4
    float* bminx  = ptsy + P * 4;              // 512
    float* bminy  = bminx + P;
    float* bmaxx  = bminy + P;
    float* bmaxy  = bmaxx + P;
    float* areaS  = bmaxy + P;
    unsigned* sup = (unsigned*)(areaS + P);    // 512*16
    int* squeue   = (int*)(sup + P * 16);      // SQ_CAP
    __shared__ int qcnt;
    __shared__ unsigned keepM[16];
    __shared__ int Vsh;

    int row = b * P + tid;

    // ---- softmax score for (row, cls) ----
    const float* lg = &logits[row * C];
    float mx = lg[0];
    #pragma unroll
    for (int i = 1; i < C; i++) mx = fmaxf(mx, lg[i]);
    float ssum = 0.0f;
    float ecls = 0.0f;
    #pragma unroll
    for (int i = 0; i < C; i++) {
        float e = expf(lg[i] - mx);
        ssum += e;
        if (i == cls) ecls = e;
    }
    float s = ecls / ssum;
    float v = (s > SCORE_THRESH) ? s : -1.0f;
    int idx = tid;

    // ---- decode (row, cls) box into smem ----
    {
        float axc = rrects[row*5+0], ayc = rrects[row*5+1];
        float aw  = rrects[row*5+2], ah  = rrects[row*5+3];
        float aa  = rrects[row*5+4];
        const float* d = &regr[row * C * REG + cls * REG];
        float dx = d[0] / 10.0f;
        float dy = d[1] / 10.0f;
        float dw = fminf(d[2] / 5.0f, BBOX_CLIP);
        float dh = fminf(d[3] / 5.0f, BBOX_CLIP);
        float da = d[4] / 3.0f;
        boxbuf[0*P + tid] = dx * aw + axc;
        boxbuf[1*P + tid] = dy * ah + ayc;
        boxbuf[2*P + tid] = expf(dw) * aw;
        boxbuf[3*P + tid] = expf(dh) * ah;
        boxbuf[4*P + tid] = da * RAD2DEG + aa;
    }

    // ---- bitonic sort 512 by (score desc, idx asc) ----
    #pragma unroll
    for (int k = 2; k <= 32; k <<= 1) {
        bool dir = ((tid & k) == 0);
        #pragma unroll
        for (int j = k >> 1; j >= 1; j >>= 1) cmp_shfl(v, idx, tid, j, dir);
    }
    #pragma unroll
    for (int k = 64; k <= 512; k <<= 1) {
        bool dir = ((tid & k) == 0);
        #pragma unroll
        for (int j = k >> 1; j >= 32; j >>= 1) {
            sv[tid] = v; si[tid] = idx;
            __syncthreads();
            int p2 = tid ^ j;
            float ov = sv[p2]; int oi = si[p2];
            bool lower = ((tid & j) == 0);
            bool before = (v > ov) || (v == ov && idx < oi);
            bool lower_before = lower ? before : !before;
            if (lower_before != dir) { v = ov; idx = oi; }
            __syncthreads();
        }
        #pragma unroll
        for (int j = 16; j >= 1; j >>= 1) cmp_shfl(v, idx, tid, j, dir);
    }
    __syncthreads();   // boxbuf writes (pre-sort) visible; sort done

    // ---- gather decoded box of ranked proposal ----
    float pp[5];
    #pragma unroll
    for (int k = 0; k < 5; k++) {
        pp[k] = boxbuf[k*P + idx];
        g_pr_s[(g * P + tid) * 5 + k] = pp[k];
    }

    // ---- corner points + aabb + area ----
    float th = pp[4] * DEG2RAD;
    float cth = cosf(th), sth = sinf(th);
    float hx = pp[2] * 0.5f, hy = pp[3] * 0.5f;
    float oxs[4] = {-hx, hx, hx, -hx};
    float oys[4] = {-hy, -hy, hy, hy};
    float cxx[4], cyy[4];
    float mnx = 1e30f, mny = 1e30f, mxx = -1e30f, mxy = -1e30f;
    #pragma unroll
    for (int i = 0; i < 4; i++) {
        float cx = pp[0] + cth * oxs[i] - sth * oys[i];
        float cy = pp[1] + sth * oxs[i] + cth * oys[i];
        cxx[i] = cx; cyy[i] = cy;
        mnx = fminf(mnx, cx); mxx = fmaxf(mxx, cx);
        mny = fminf(mny, cy); mxy = fmaxf(mxy, cy);
    }
    // clipped aabb for output
    g_bx_s[(g * P + tid) * 4 + 0] = fminf(fmaxf(mnx, 0.0f), IMW_M1);
    g_bx_s[(g * P + tid) * 4 + 1] = fminf(fmaxf(mny, 0.0f), IMH_M1);
    g_bx_s[(g * P + tid) * 4 + 2] = fminf(fmaxf(mxx, 0.0f), IMW_M1);
    g_bx_s[(g * P + tid) * 4 + 3] = fminf(fmaxf(mxy, 0.0f), IMH_M1);

    __syncthreads();   // all gathers from boxbuf done; safe to reuse nothing (separate bufs)

    #pragma unroll
    for (int i = 0; i < 4; i++) { ptsx[tid*4+i] = cxx[i]; ptsy[tid*4+i] = cyy[i]; }
    bminx[tid] = mnx; bmaxx[tid] = mxx;
    bminy[tid] = mny; bmaxy[tid] = mxy;
    areaS[tid] = pp[2] * pp[3];
    #pragma unroll
    for (int k = 0; k < 16; k++) sup[tid * 16 + k] = 0u;

    bool valid = v > SCORE_THRESH;
    int V = __syncthreads_count(valid);   // valid entries form a sorted prefix
    if (tid == 0) { qcnt = 0; Vsh = V; }
    __syncthreads();

    // ---- phase 1: AABB + IoU-upper-bound precheck -> pair queue ----
    int lane = tid & 31;
    long long M = (long long)V * (V - 1) / 2;
    for (long long base = 0; base < M; base += blockDim.x) {
        long long t = base + tid;
        bool push = false; int pi = 0, pj = 0;
        if (t < M) {
            int i = (int)((sqrtf(8.0f * (float)t + 1.0f) + 1.0f) * 0.5f);
            while ((long long)i * (i - 1) / 2 > t) i--;
            while ((long long)(i + 1) * i / 2 <= t) i++;
            int j = (int)(t - (long long)i * (i - 1) / 2);
            float iw = fminf(bmaxx[i], bmaxx[j]) - fmaxf(bminx[i], bminx[j]);
            float ih = fminf(bmaxy[i], bmaxy[j]) - fmaxf(bminy[i], bminy[j]);
            if (iw > 0.0f && ih > 0.0f) {
                float ai = areaS[i], aj = areaS[j];
                float ub = fminf(iw * ih, fminf(ai, aj));
                float bound = ub / (ai + aj - ub + 1e-8f);
                push = bound > NMS_THR * 0.999f;   // conservative: can't miss iou>thr
            }
            pi = i; pj = j;
        }
        unsigned mb = __ballot_sync(FULLM, push);
        if (mb) {
            int ldr = __ffs(mb) - 1;
            int basep = 0;
            if (lane == ldr) basep = atomicAdd(&qcnt, __popc(mb));
            basep = __shfl_sync(FULLM, basep, ldr);
            if (push) {
                int pos = basep + __popc(mb & ((1u << lane) - 1u));
                int enc = (pi << 16) | pj;
                if (pos < SQ_CAP) squeue[pos] = enc;
                else g_queue[g * QCAP + (pos - SQ_CAP)] = enc;
            }
        }
    }
    __syncthreads();

    // ---- phase 2: exact IoU over surviving pairs ----
    int nq = qcnt;
    for (int q = tid; q < nq; q += blockDim.x) {
        int ij = (q < SQ_CAP) ? squeue[q] : g_queue[g * QCAP + (q - SQ_CAP)];
        int i = ij >> 16, j = ij & 0xffff;
        float inter = inter_area(&ptsx[i * 4], &ptsy[i * 4], &ptsx[j * 4], &ptsy[j * 4]);
        float iou = inter / (areaS[i] + areaS[j] - inter + 1e-8f);
        if (iou > NMS_THR) atomicOr(&sup[i * 16 + (j >> 5)], 1u << (j & 31));
    }
    __syncthreads();

    // ---- phase 3: greedy scan (warp 0, prefetched) ----
    if (tid < 32) {
        unsigned kw = 0;
        int VV = Vsh;
        unsigned srow = (tid < 16 && VV > 0) ? sup[tid] : 0u;
        for (int i = 0; i < VV; i++) {
            unsigned nrow = (tid < 16 && (i + 1) < VV) ? sup[(i + 1) * 16 + tid] : 0u;
            bool any = __any_sync(FULLM, (kw & srow) != 0u);
            if (!any && tid == (i >> 5)) kw |= 1u << (i & 31);
            srow = nrow;
        }
        if (tid < 16) keepM[tid] = kw;
    }
    __syncthreads();

    bool kept = (tid < Vsh) && ((keepM[tid >> 5] >> (tid & 31)) & 1u);
    g_msk[g * P + tid] = kept ? v : -1.0f;
}

// ---------------- kernel 4: radix-threshold top-100 + output ----------------
#define K4_THREADS 1024
#define K4_PER (((C-1)*P) / K4_THREADS)   // 10 (exact)
#define CANDCAP 256

__global__ void k4_topk(float* __restrict__ out)
{
    int b = blockIdx.x;
    int tid = threadIdx.x;
    const int TOT = (C - 1) * P;   // 10240
    int lane = tid & 31;
    int wid = tid >> 5;

    float v[K4_PER];
    unsigned key[K4_PER];
    #pragma unroll
    for (int i = 0; i < K4_PER; i++) {
        float x = g_msk[b * TOT + tid + i * K4_THREADS];
        v[i] = x;
        unsigned bb = __float_as_uint(x);
        key[i] = bb ^ ((bb & 0x80000000u) ? 0xFFFFFFFFu : 0x80000000u);
    }

    __shared__ int partial[2][32];
    __shared__ int ncand;
    __shared__ float cv[CANDCAP];
    __shared__ int   ci[CANDCAP];

    if (tid == 0) ncand = 0;

    // binary search with early exit: find cur with DET <= count(key>=cur) <= CANDCAP
    unsigned cur = 0u;
    int curcnt = TOT;
    for (int bit = 31; bit >= 0; bit--) {
        unsigned trial = cur | (1u << bit);
        int c = 0;
        #pragma unroll
        for (int i = 0; i < K4_PER; i++) c += (key[i] >= trial);
        #pragma unroll
        for (int o = 16; o; o >>= 1) c += __shfl_xor_sync(FULLM, c, o);
        if (lane == 0) partial[bit & 1][wid] = c;
        __syncthreads();
        int t = partial[bit & 1][lane];
        #pragma unroll
        for (int o = 16; o; o >>= 1) t += __shfl_xor_sync(FULLM, t, o);
        if (t >= DET) { cur = trial; curcnt = t; }
        if (curcnt <= CANDCAP) break;
    }
    unsigned kthr = cur;

    // collect candidates (ballot-aggregated): key >= kthr AND positive value
    __syncthreads();
    #pragma unroll
    for (int i = 0; i < K4_PER; i++) {
        bool cand = (key[i] >= kthr) && (v[i] > 0.0f);
        unsigned mb = __ballot_sync(FULLM, cand);
        if (mb) {
            int ldr = __ffs(mb) - 1;
            int basep = 0;
            if (lane == ldr) basep = atomicAdd(&ncand, __popc(mb));
            basep = __shfl_sync(FULLM, basep, ldr);
            if (cand) {
                int pos = basep + __popc(mb & ((1u << lane) - 1u));
                if (pos < CANDCAP) { cv[pos] = v[i]; ci[pos] = tid + i * K4_THREADS; }
            }
        }
    }
    __syncthreads();
    int nc = min(ncand, CANDCAP);

    // bitonic sort CANDCAP=256 candidates (regs + shfl; smem for j>=32)
    float mv = -1e30f; int mi = 0x7fffffff;
    if (tid < CANDCAP && tid < nc) { mv = cv[tid]; mi = ci[tid]; }
    __syncthreads();

    if (tid < CANDCAP) {
        #pragma unroll
        for (int k = 2; k <= 32; k <<= 1) {
            bool dir = ((tid & k) == 0);
            #pragma unroll
            for (int j = k >> 1; j >= 1; j >>= 1) cmp_shfl(mv, mi, tid, j, dir);
        }
    }
    #pragma unroll
    for (int k = 64; k <= CANDCAP; k <<= 1) {
        bool dir = ((tid & k) == 0);
        #pragma unroll
        for (int j = k >> 1; j >= 32; j >>= 1) {
            if (tid < CANDCAP) { cv[tid] = mv; ci[tid] = mi; }
            __syncthreads();
            if (tid < CANDCAP) {
                int p2 = tid ^ j;
                float ov = cv[p2]; int oi = ci[p2];
                bool lower = ((tid & j) == 0);
                bool before = (mv > ov) || (mv == ov && mi < oi);
                bool lower_before = lower ? before : !before;
                if (lower_before != dir) { mv = ov; mi = oi; }
            }
            __syncthreads();
        }
        if (tid < CANDCAP) {
            #pragma unroll
            for (int j = 16; j >= 1; j >>= 1) cmp_shfl(mv, mi, tid, j, dir);
        }
    }

    // output layout (float32): bb [B,DET,4] | rr [B,DET,5] | sc [B,DET] | lab [B,DET]
    if (tid < DET) {
        float val = mv;
        int fi = (mi == 0x7fffffff) ? 0 : mi;
        bool ok = val > 0.0f;
        int cls = fi / P + 1;
        int gi = b * TOT + fi;
        int o = b * DET + tid;
        #pragma unroll
        for (int jj = 0; jj < 4; jj++)
            out[o * 4 + jj] = ok ? g_bx_s[gi * 4 + jj] : 0.0f;
        #pragma unroll
        for (int jj = 0; jj < 5; jj++)
            out[B * DET * 4 + o * 5 + jj] = ok ? g_pr_s[gi * 5 + jj] : 0.0f;
        out[B * DET * 9 + o] = ok ? val : 0.0f;
        out[B * DET * 10 + o] = ok ? (float)cls : 0.0f;
    }
}

// ---------------- launch ----------------
extern "C" void kernel_launch(void* const* d_in, const int* in_sizes, int n_in,
                              void* d_out, int out_size)
{
    const float* logits = (const float*)d_in[0];
    const float* regr   = (const float*)d_in[1];
    const float* rrects = (const float*)d_in[2];
    float* out = (float*)d_out;

    const int SMEM123 = (P + 5*P + P*4*2 + 5*P) * (int)sizeof(float)
                      + P * (int)sizeof(int)
                      + P*16*(int)sizeof(unsigned) + SQ_CAP*(int)sizeof(int);
    cudaFuncSetAttribute(k123_sortnms, cudaFuncAttributeMaxDynamicSharedMemorySize, SMEM123);

    k123_sortnms<<<NGRP, P, SMEM123>>>(logits, regr, rrects);
    k4_topk<<<B, K4_THREADS>>>(out);
}